// round 2
// baseline (speedup 1.0000x reference)
#include <cuda_runtime.h>
#include <cuda_bf16.h>

#define N_NODES 100000
#define N_EDGES 500000
#define ET 3
#define C 128
#define LN_EPS 1e-5f
#define L2_EPS 1e-12f

#define BM 128
#define BN 128
#define BK 16

// ---------------- scratch (static device globals; no allocation) ----------------
__device__ float g_msg[N_NODES * C];
__device__ float g_agg0[N_NODES * C];
__device__ float g_agg1[N_NODES * C];
__device__ float g_agg2[N_NODES * C];
__device__ float g_h[N_NODES * C];
__device__ float g_accb[N_NODES * C];
__device__ float g_wsum[2 * C * C];
__device__ float g_bsum[2 * C];
__device__ float g_invdeg[ET * N_NODES];
__device__ int g_cnt[ET * N_NODES];
__device__ int g_cur[ET * N_NODES];
__device__ int g_rowptr[ET * (N_NODES + 1)];
__device__ int g_col[ET * N_EDGES];
__device__ int g_bofs[ET * 128];

// ---------------- CSR build ----------------
__global__ void k_zero_int() {
    int i = blockIdx.x * blockDim.x + threadIdx.x;
    if (i < ET * N_NODES) { g_cnt[i] = 0; g_cur[i] = 0; }
}
__global__ void k_zero_acc() {
    int i = blockIdx.x * blockDim.x + threadIdx.x;
    if (i < N_NODES * C) g_accb[i] = 0.f;
}
__global__ void k_hist(const int* __restrict__ edges) {
    int i = blockIdx.x * blockDim.x + threadIdx.x;
    if (i >= ET * N_EDGES) return;
    int t = i / N_EDGES, e = i - t * N_EDGES;
    int dst = edges[(t * 2 + 1) * N_EDGES + e];
    atomicAdd(&g_cnt[t * N_NODES + dst], 1);
}
__global__ void k_scan1() {
    int t = blockIdx.y;
    int i = blockIdx.x * 1024 + threadIdx.x;
    __shared__ int sm[1024];
    int v = (i < N_NODES) ? g_cnt[t * N_NODES + i] : 0;
    sm[threadIdx.x] = v;
    __syncthreads();
    for (int off = 1; off < 1024; off <<= 1) {
        int add = (threadIdx.x >= off) ? sm[threadIdx.x - off] : 0;
        __syncthreads();
        sm[threadIdx.x] += add;
        __syncthreads();
    }
    if (i < N_NODES) g_rowptr[t * (N_NODES + 1) + i] = sm[threadIdx.x] - v;  // exclusive
    if (threadIdx.x == 1023) g_bofs[t * 128 + blockIdx.x] = sm[1023];
}
__global__ void k_scan2() {
    int t = threadIdx.x;
    if (t >= ET) return;
    int nb = (N_NODES + 1023) / 1024;
    int run = 0;
    for (int b = 0; b < nb; b++) { int v = g_bofs[t * 128 + b]; g_bofs[t * 128 + b] = run; run += v; }
    g_rowptr[t * (N_NODES + 1) + N_NODES] = run;
}
__global__ void k_scan3() {
    int t = blockIdx.y;
    int i = blockIdx.x * 1024 + threadIdx.x;
    if (i < N_NODES) g_rowptr[t * (N_NODES + 1) + i] += g_bofs[t * 128 + blockIdx.x];
}
__global__ void k_invdeg() {
    int i = blockIdx.x * blockDim.x + threadIdx.x;
    if (i < ET * N_NODES) {
        int c = g_cnt[i];
        g_invdeg[i] = 1.0f / (float)(c > 1 ? c : 1);
    }
}
__global__ void k_scatter(const int* __restrict__ edges) {
    int i = blockIdx.x * blockDim.x + threadIdx.x;
    if (i >= ET * N_EDGES) return;
    int t = i / N_EDGES, e = i - t * N_EDGES;
    int src = edges[t * 2 * N_EDGES + e];
    int dst = edges[(t * 2 + 1) * N_EDGES + e];
    int pos = g_rowptr[t * (N_NODES + 1) + dst] + atomicAdd(&g_cur[t * N_NODES + dst], 1);
    g_col[t * N_EDGES + pos] = src;
}

// ---------------- weight pre-sum (layers 1..2 combine h@Wr across edge types) ----------------
__global__ void k_wsum(const float* __restrict__ Wr, const float* __restrict__ bl) {
    int i = blockIdx.x * blockDim.x + threadIdx.x;
    if (i < 2 * C * C) {
        int l = i / (C * C), idx = i - l * (C * C);
        g_wsum[i] = Wr[(l * 3 + 0) * C * C + idx] + Wr[(l * 3 + 1) * C * C + idx]
                  + Wr[(l * 3 + 2) * C * C + idx];
    }
    if (i < 2 * C) {
        int l = i / C, cc = i - l * C;
        g_bsum[i] = bl[(l * 3 + 0) * C + cc] + bl[(l * 3 + 1) * C + cc] + bl[(l * 3 + 2) * C + cc];
    }
}

// ---------------- mean aggregation over CSR (warp per node) ----------------
__global__ void k_aggregate(int t, const float* __restrict__ feat, float* __restrict__ out) {
    int w = (blockIdx.x * blockDim.x + threadIdx.x) >> 5;
    int lane = threadIdx.x & 31;
    if (w >= N_NODES) return;
    const int* rp = &g_rowptr[t * (N_NODES + 1)];
    int s = rp[w], e = rp[w + 1];
    const int* col = &g_col[t * N_EDGES];
    float4 acc = make_float4(0.f, 0.f, 0.f, 0.f);
    for (int j = s; j < e; j++) {
        int src = col[j];
        float4 v = *reinterpret_cast<const float4*>(&feat[src * C + lane * 4]);
        acc.x += v.x; acc.y += v.y; acc.z += v.z; acc.w += v.w;
    }
    float inv = g_invdeg[t * N_NODES + w];
    acc.x *= inv; acc.y *= inv; acc.z *= inv; acc.w *= inv;
    *reinterpret_cast<float4*>(&out[w * C + lane * 4]) = acc;
}

// ---------------- fused relu + LayerNorm (warp per row) ----------------
__global__ void k_relu_ln(const float* __restrict__ in, float* __restrict__ out,
                          const float* __restrict__ g, const float* __restrict__ b, float scale) {
    int w = (blockIdx.x * blockDim.x + threadIdx.x) >> 5;
    int lane = threadIdx.x & 31;
    if (w >= N_NODES) return;
    float4 v = *reinterpret_cast<const float4*>(&in[w * C + lane * 4]);
    v.x = fmaxf(v.x * scale, 0.f);
    v.y = fmaxf(v.y * scale, 0.f);
    v.z = fmaxf(v.z * scale, 0.f);
    v.w = fmaxf(v.w * scale, 0.f);
    float s = v.x + v.y + v.z + v.w;
    #pragma unroll
    for (int off = 16; off > 0; off >>= 1) s += __shfl_xor_sync(0xffffffffu, s, off);
    float mean = s * (1.f / 128.f);
    float dx = v.x - mean, dy = v.y - mean, dz = v.z - mean, dw = v.w - mean;
    float ss = dx * dx + dy * dy + dz * dz + dw * dw;
    #pragma unroll
    for (int off = 16; off > 0; off >>= 1) ss += __shfl_xor_sync(0xffffffffu, ss, off);
    float rstd = rsqrtf(ss * (1.f / 128.f) + LN_EPS);
    float4 gg = *reinterpret_cast<const float4*>(&g[lane * 4]);
    float4 bb = *reinterpret_cast<const float4*>(&b[lane * 4]);
    float4 o;
    o.x = dx * rstd * gg.x + bb.x;
    o.y = dy * rstd * gg.y + bb.y;
    o.z = dz * rstd * gg.z + bb.z;
    o.w = dw * rstd * gg.w + bb.w;
    *reinterpret_cast<float4*>(&out[w * C + lane * 4]) = o;
}

// ---------------- tiled SGEMM over concatenated-K chunks, with fused epilogues ----------------
// out[N,128] = sum_chunks Achunk[N,128] @ Wchunk[128,128]  (+bias, then epilogue)
// mode 0: out = relu(val)          (projection)
// mode 1: out += L2-rownorm(val)   (layer-0 per-type accumulate)
// mode 2: out = val * (1/3)        (layers 1..2 combined)
__global__ __launch_bounds__(256) void k_gemm(
    const float* __restrict__ A0, const float* __restrict__ A1,
    const float* __restrict__ A2, const float* __restrict__ A3,
    const float* __restrict__ W0, const float* __restrict__ W1,
    const float* __restrict__ W2, const float* __restrict__ W3,
    const float* __restrict__ bias, float* __restrict__ out,
    int nChunks, int mode)
{
    __shared__ float As[BK][BM];
    __shared__ float Ws[BK][BN];
    const float* Aarr[4] = {A0, A1, A2, A3};
    const float* Warr[4] = {W0, W1, W2, W3};
    int tid = threadIdx.x;
    int tx = tid & 15, ty = tid >> 4;
    int row0 = blockIdx.x * BM;

    float acc[8][8];
    #pragma unroll
    for (int i = 0; i < 8; i++)
        #pragma unroll
        for (int j = 0; j < 8; j++) acc[i][j] = 0.f;

    int K = nChunks * C;
    for (int k0 = 0; k0 < K; k0 += BK) {
        const float* Ac = Aarr[k0 >> 7];
        const float* Wc = Warr[k0 >> 7];
        int kc = k0 & (C - 1);
        // A tile: 128 rows x 16 cols, stored transposed As[k][row]
        #pragma unroll
        for (int q = 0; q < 2; q++) {
            int f = tid + q * 256;
            int ar = f >> 2, c4 = (f & 3) * 4;
            int gr = row0 + ar;
            float4 v = make_float4(0.f, 0.f, 0.f, 0.f);
            if (gr < N_NODES) v = *reinterpret_cast<const float4*>(&Ac[gr * C + kc + c4]);
            As[c4 + 0][ar] = v.x;
            As[c4 + 1][ar] = v.y;
            As[c4 + 2][ar] = v.z;
            As[c4 + 3][ar] = v.w;
        }
        // W tile: 16 rows x 128 cols, direct
        #pragma unroll
        for (int q = 0; q < 2; q++) {
            int f = tid + q * 256;
            int wr = f >> 5, wc = (f & 31) * 4;
            *reinterpret_cast<float4*>(&Ws[wr][wc]) =
                *reinterpret_cast<const float4*>(&Wc[(kc + wr) * C + wc]);
        }
        __syncthreads();
        #pragma unroll
        for (int k = 0; k < BK; k++) {
            float a[8], b[8];
            *reinterpret_cast<float4*>(&a[0]) = *reinterpret_cast<float4*>(&As[k][ty * 8]);
            *reinterpret_cast<float4*>(&a[4]) = *reinterpret_cast<float4*>(&As[k][ty * 8 + 4]);
            *reinterpret_cast<float4*>(&b[0]) = *reinterpret_cast<float4*>(&Ws[k][tx * 8]);
            *reinterpret_cast<float4*>(&b[4]) = *reinterpret_cast<float4*>(&Ws[k][tx * 8 + 4]);
            #pragma unroll
            for (int i = 0; i < 8; i++)
                #pragma unroll
                for (int j = 0; j < 8; j++)
                    acc[i][j] += a[i] * b[j];
        }
        __syncthreads();
    }

    // bias
    float bv[8];
    #pragma unroll
    for (int j = 0; j < 8; j++) bv[j] = bias[tx * 8 + j];
    #pragma unroll
    for (int i = 0; i < 8; i++)
        #pragma unroll
        for (int j = 0; j < 8; j++) acc[i][j] += bv[j];

    if (mode == 0) {
        #pragma unroll
        for (int i = 0; i < 8; i++) {
            int gr = row0 + ty * 8 + i;
            if (gr < N_NODES) {
                float4 o0 = make_float4(fmaxf(acc[i][0], 0.f), fmaxf(acc[i][1], 0.f),
                                        fmaxf(acc[i][2], 0.f), fmaxf(acc[i][3], 0.f));
                float4 o1 = make_float4(fmaxf(acc[i][4], 0.f), fmaxf(acc[i][5], 0.f),
                                        fmaxf(acc[i][6], 0.f), fmaxf(acc[i][7], 0.f));
                *reinterpret_cast<float4*>(&out[gr * C + tx * 8]) = o0;
                *reinterpret_cast<float4*>(&out[gr * C + tx * 8 + 4]) = o1;
            }
        }
    } else if (mode == 2) {
        const float sc = 1.f / 3.f;
        #pragma unroll
        for (int i = 0; i < 8; i++) {
            int gr = row0 + ty * 8 + i;
            if (gr < N_NODES) {
                float4 o0 = make_float4(acc[i][0] * sc, acc[i][1] * sc, acc[i][2] * sc, acc[i][3] * sc);
                float4 o1 = make_float4(acc[i][4] * sc, acc[i][5] * sc, acc[i][6] * sc, acc[i][7] * sc);
                *reinterpret_cast<float4*>(&out[gr * C + tx * 8]) = o0;
                *reinterpret_cast<float4*>(&out[gr * C + tx * 8 + 4]) = o1;
            }
        }
    } else {
        // mode 1: per-row L2 normalize then accumulate
        float* red = &As[0][0];   // 128 rows x 16 partials
        #pragma unroll
        for (int i = 0; i < 8; i++) {
            float ss = 0.f;
            #pragma unroll
            for (int j = 0; j < 8; j++) ss += acc[i][j] * acc[i][j];
            red[(ty * 8 + i) * 16 + tx] = ss;
        }
        __syncthreads();
        float* invn = &Ws[0][0];  // 128 inverse norms
        if (tid < 128) {
            float s = 0.f;
            #pragma unroll
            for (int xx = 0; xx < 16; xx++) s += red[tid * 16 + xx];
            invn[tid] = 1.f / fmaxf(sqrtf(s), L2_EPS);
        }
        __syncthreads();
        #pragma unroll
        for (int i = 0; i < 8; i++) {
            int gr = row0 + ty * 8 + i;
            if (gr < N_NODES) {
                float iv = invn[ty * 8 + i];
                #pragma unroll
                for (int j = 0; j < 8; j++)
                    out[gr * C + tx * 8 + j] += acc[i][j] * iv;
            }
        }
    }
}

// ---------------- host orchestration ----------------
extern "C" void kernel_launch(void* const* d_in, const int* in_sizes, int n_in,
                              void* d_out, int out_size) {
    const float* x    = (const float*)d_in[0];
    const int*   edges = (const int*)d_in[1];
    const float* Wp   = (const float*)d_in[2];
    const float* bp   = (const float*)d_in[3];
    const float* Wl0  = (const float*)d_in[4];
    const float* bl0  = (const float*)d_in[5];
    const float* Wr0  = (const float*)d_in[6];
    const float* Wl   = (const float*)d_in[7];
    const float* bl   = (const float*)d_in[8];
    const float* Wr   = (const float*)d_in[9];
    const float* ln_g = (const float*)d_in[10];
    const float* ln_b = (const float*)d_in[11];
    float* out = (float*)d_out;

    void* p;
    float *msg, *agg0, *agg1, *agg2, *h, *accb, *wsum, *bsum;
    cudaGetSymbolAddress(&p, g_msg);  msg  = (float*)p;
    cudaGetSymbolAddress(&p, g_agg0); agg0 = (float*)p;
    cudaGetSymbolAddress(&p, g_agg1); agg1 = (float*)p;
    cudaGetSymbolAddress(&p, g_agg2); agg2 = (float*)p;
    cudaGetSymbolAddress(&p, g_h);    h    = (float*)p;
    cudaGetSymbolAddress(&p, g_accb); accb = (float*)p;
    cudaGetSymbolAddress(&p, g_wsum); wsum = (float*)p;
    cudaGetSymbolAddress(&p, g_bsum); bsum = (float*)p;

    int nbScan = (N_NODES + 1023) / 1024;
    dim3 gScan(nbScan, ET);

    // CSR build + prep
    k_zero_int<<<(ET * N_NODES + 255) / 256, 256>>>();
    k_zero_acc<<<(N_NODES * C + 255) / 256, 256>>>();
    k_hist<<<(ET * N_EDGES + 255) / 256, 256>>>(edges);
    k_scan1<<<gScan, 1024>>>();
    k_scan2<<<1, 32>>>();
    k_scan3<<<gScan, 1024>>>();
    k_invdeg<<<(ET * N_NODES + 255) / 256, 256>>>();
    k_scatter<<<(ET * N_EDGES + 255) / 256, 256>>>(edges);
    k_wsum<<<(2 * C * C + 255) / 256, 256>>>(Wr, bl);

    int gGemm = (N_NODES + BM - 1) / BM;
    int gWarp = (N_NODES * 32 + 255) / 256;

    // ---- layer 0 (project=True, normalize=True, per edge type) ----
    for (int t = 0; t < ET; t++) {
        k_gemm<<<gGemm, 256>>>(x, 0, 0, 0,
                               Wp + t * C * C, 0, 0, 0,
                               bp + t * C, msg, 1, 0);            // msg = relu(x@Wp+bp)
        k_aggregate<<<gWarp, 256>>>(t, msg, agg0);                // mean aggr of msg
        k_gemm<<<gGemm, 256>>>(agg0, x, 0, 0,
                               Wl0 + t * C * C, Wr0 + t * C * C, 0, 0,
                               bl0 + t * C, accb, 2, 1);          // accb += norm(agg@Wl0 + x@Wr0 + b)
    }
    k_relu_ln<<<gWarp, 256>>>(accb, h, ln_g, ln_b, 1.f / 3.f);    // h = LN(relu(acc/3))

    // ---- layers 1..2 ----
    float* aggs[3] = {agg0, agg1, agg2};
    for (int l = 0; l < 2; l++) {
        for (int t = 0; t < ET; t++)
            k_aggregate<<<gWarp, 256>>>(t, h, aggs[t]);
        float* dst = (l == 0) ? accb : out;
        k_gemm<<<gGemm, 256>>>(agg0, agg1, agg2, h,
                               Wl + (l * 3 + 0) * C * C, Wl + (l * 3 + 1) * C * C,
                               Wl + (l * 3 + 2) * C * C, wsum + l * C * C,
                               bsum + l * C, dst, 4, 2);          // (Σ agg@Wl + h@ΣWr + Σb)/3
        if (l == 0)
            k_relu_ln<<<gWarp, 256>>>(accb, h, ln_g + C, ln_b + C, 1.f);
    }
}

// round 5
// speedup vs baseline: 1.4918x; 1.4918x over previous
#include <cuda_runtime.h>
#include <cuda_bf16.h>
#include <cstdint>

#define N_NODES 100000
#define N_EDGES 500000
#define ET 3
#define C 128
#define LN_EPS 1e-5f
#define L2_EPS 1e-12f

#define PITCH 40                      // halves per smem row (bank-conflict-free)
#define SMEM_MMA_BYTES (4 * 128 * PITCH * 2)   // Ahi, Alo, Bhi, Blo

// ---------------- scratch (static device globals; no allocation) ----------------
__device__ float g_msg[N_NODES * C];
__device__ float g_agg0[N_NODES * C];
__device__ float g_agg1[N_NODES * C];
__device__ float g_agg2[N_NODES * C];
__device__ float g_h[N_NODES * C];
__device__ float g_accb[N_NODES * C];
__device__ float g_wsum[2 * C * C];
__device__ float g_bsum[2 * C];
__device__ float g_invdeg[ET * N_NODES];
__device__ int g_cnt[ET * N_NODES];
__device__ int g_cur[ET * N_NODES];
__device__ int g_rowptr[ET * (N_NODES + 1)];
__device__ int g_col[ET * N_EDGES];
__device__ int g_bofs[ET * 128];

// ---------------- CSR build ----------------
__global__ void k_zero_int() {
    int i = blockIdx.x * blockDim.x + threadIdx.x;
    if (i < ET * N_NODES) { g_cnt[i] = 0; g_cur[i] = 0; }
}
__global__ void k_zero_acc() {
    int i = blockIdx.x * blockDim.x + threadIdx.x;
    if (i < N_NODES * C) g_accb[i] = 0.f;
}
__global__ void k_hist(const int* __restrict__ edges) {
    int i = blockIdx.x * blockDim.x + threadIdx.x;
    if (i >= ET * N_EDGES) return;
    int t = i / N_EDGES, e = i - t * N_EDGES;
    int dst = edges[(t * 2 + 1) * N_EDGES + e];
    atomicAdd(&g_cnt[t * N_NODES + dst], 1);
}
__global__ void k_scan1() {
    int t = blockIdx.y;
    int i = blockIdx.x * 1024 + threadIdx.x;
    __shared__ int sm[1024];
    int v = (i < N_NODES) ? g_cnt[t * N_NODES + i] : 0;
    sm[threadIdx.x] = v;
    __syncthreads();
    for (int off = 1; off < 1024; off <<= 1) {
        int add = (threadIdx.x >= off) ? sm[threadIdx.x - off] : 0;
        __syncthreads();
        sm[threadIdx.x] += add;
        __syncthreads();
    }
    if (i < N_NODES) g_rowptr[t * (N_NODES + 1) + i] = sm[threadIdx.x] - v;
    if (threadIdx.x == 1023) g_bofs[t * 128 + blockIdx.x] = sm[1023];
}
__global__ void k_scan2() {
    int t = threadIdx.x;
    if (t >= ET) return;
    int nb = (N_NODES + 1023) / 1024;
    int run = 0;
    for (int b = 0; b < nb; b++) { int v = g_bofs[t * 128 + b]; g_bofs[t * 128 + b] = run; run += v; }
    g_rowptr[t * (N_NODES + 1) + N_NODES] = run;
}
__global__ void k_scan3() {
    int t = blockIdx.y;
    int i = blockIdx.x * 1024 + threadIdx.x;
    if (i < N_NODES) g_rowptr[t * (N_NODES + 1) + i] += g_bofs[t * 128 + blockIdx.x];
}
__global__ void k_invdeg() {
    int i = blockIdx.x * blockDim.x + threadIdx.x;
    if (i < ET * N_NODES) {
        int c = g_cnt[i];
        g_invdeg[i] = 1.0f / (float)(c > 1 ? c : 1);
    }
}
__global__ void k_scatter(const int* __restrict__ edges) {
    int i = blockIdx.x * blockDim.x + threadIdx.x;
    if (i >= ET * N_EDGES) return;
    int t = i / N_EDGES, e = i - t * N_EDGES;
    int src = edges[t * 2 * N_EDGES + e];
    int dst = edges[(t * 2 + 1) * N_EDGES + e];
    int pos = g_rowptr[t * (N_NODES + 1) + dst] + atomicAdd(&g_cur[t * N_NODES + dst], 1);
    g_col[t * N_EDGES + pos] = src;
}

// ---------------- weight pre-sum ----------------
__global__ void k_wsum(const float* __restrict__ Wr, const float* __restrict__ bl) {
    int i = blockIdx.x * blockDim.x + threadIdx.x;
    if (i < 2 * C * C) {
        int l = i / (C * C), idx = i - l * (C * C);
        g_wsum[i] = Wr[(l * 3 + 0) * C * C + idx] + Wr[(l * 3 + 1) * C * C + idx]
                  + Wr[(l * 3 + 2) * C * C + idx];
    }
    if (i < 2 * C) {
        int l = i / C, cc = i - l * C;
        g_bsum[i] = bl[(l * 3 + 0) * C + cc] + bl[(l * 3 + 1) * C + cc] + bl[(l * 3 + 2) * C + cc];
    }
}

// ---------------- mean aggregation over CSR (warp per node) ----------------
__global__ void k_aggregate(int t, const float* __restrict__ feat, float* __restrict__ out) {
    int w = (blockIdx.x * blockDim.x + threadIdx.x) >> 5;
    int lane = threadIdx.x & 31;
    if (w >= N_NODES) return;
    const int* rp = &g_rowptr[t * (N_NODES + 1)];
    int s = rp[w], e = rp[w + 1];
    const int* col = &g_col[t * N_EDGES];
    float4 acc = make_float4(0.f, 0.f, 0.f, 0.f);
    for (int j = s; j < e; j++) {
        int src = col[j];
        float4 v = *reinterpret_cast<const float4*>(&feat[src * C + lane * 4]);
        acc.x += v.x; acc.y += v.y; acc.z += v.z; acc.w += v.w;
    }
    float inv = g_invdeg[t * N_NODES + w];
    acc.x *= inv; acc.y *= inv; acc.z *= inv; acc.w *= inv;
    *reinterpret_cast<float4*>(&out[w * C + lane * 4]) = acc;
}

// ---------------- fused relu + LayerNorm (warp per row) ----------------
__global__ void k_relu_ln(const float* __restrict__ in, float* __restrict__ out,
                          const float* __restrict__ g, const float* __restrict__ b, float scale) {
    int w = (blockIdx.x * blockDim.x + threadIdx.x) >> 5;
    int lane = threadIdx.x & 31;
    if (w >= N_NODES) return;
    float4 v = *reinterpret_cast<const float4*>(&in[w * C + lane * 4]);
    v.x = fmaxf(v.x * scale, 0.f);
    v.y = fmaxf(v.y * scale, 0.f);
    v.z = fmaxf(v.z * scale, 0.f);
    v.w = fmaxf(v.w * scale, 0.f);
    float s = v.x + v.y + v.z + v.w;
    #pragma unroll
    for (int off = 16; off > 0; off >>= 1) s += __shfl_xor_sync(0xffffffffu, s, off);
    float mean = s * (1.f / 128.f);
    float dx = v.x - mean, dy = v.y - mean, dz = v.z - mean, dw = v.w - mean;
    float ss = dx * dx + dy * dy + dz * dz + dw * dw;
    #pragma unroll
    for (int off = 16; off > 0; off >>= 1) ss += __shfl_xor_sync(0xffffffffu, ss, off);
    float rstd = rsqrtf(ss * (1.f / 128.f) + LN_EPS);
    float4 gg = *reinterpret_cast<const float4*>(&g[lane * 4]);
    float4 bb = *reinterpret_cast<const float4*>(&b[lane * 4]);
    float4 o;
    o.x = dx * rstd * gg.x + bb.x;
    o.y = dy * rstd * gg.y + bb.y;
    o.z = dz * rstd * gg.z + bb.z;
    o.w = dw * rstd * gg.w + bb.w;
    *reinterpret_cast<float4*>(&out[w * C + lane * 4]) = o;
}

// ---------------- split-bf16 tensor-core GEMM (mma.sync m16n8k16) ----------------
// out[N,128] = sum_chunks Achunk[N,128] @ Wchunk[128,128]  (+bias, then epilogue)
// mode 0: out = relu(val)   mode 1: out += L2-rownorm(val)   mode 2: out = val/3
__device__ __forceinline__ void mma_bf16(float* d, const uint32_t* a, uint32_t b0, uint32_t b1) {
    asm volatile(
        "mma.sync.aligned.m16n8k16.row.col.f32.bf16.bf16.f32 "
        "{%0,%1,%2,%3}, {%4,%5,%6,%7}, {%8,%9}, {%0,%1,%2,%3};"
        : "+f"(d[0]), "+f"(d[1]), "+f"(d[2]), "+f"(d[3])
        : "r"(a[0]), "r"(a[1]), "r"(a[2]), "r"(a[3]), "r"(b0), "r"(b1));
}

__device__ __forceinline__ void split2(float x, __nv_bfloat16& hi, __nv_bfloat16& lo) {
    hi = __float2bfloat16_rn(x);
    lo = __float2bfloat16_rn(x - __bfloat162float(hi));
}

__global__ __launch_bounds__(256, 2) void k_mma(
    const float* __restrict__ A0, const float* __restrict__ A1,
    const float* __restrict__ A2, const float* __restrict__ A3,
    const float* __restrict__ W0, const float* __restrict__ W1,
    const float* __restrict__ W2, const float* __restrict__ W3,
    const float* __restrict__ bias, float* __restrict__ out,
    int nChunks, int mode)
{
    extern __shared__ char smem[];
    __nv_bfloat16* Ahi = (__nv_bfloat16*)smem;
    __nv_bfloat16* Alo = Ahi + 128 * PITCH;
    __nv_bfloat16* Bhi = Alo + 128 * PITCH;
    __nv_bfloat16* Blo = Bhi + 128 * PITCH;

    int t = threadIdx.x;
    int lane = t & 31, wid = t >> 5;
    int g = lane >> 2, tg = lane & 3;
    int wm = wid & 3, wn = wid >> 2;      // warp tile: rows wm*32..+31, cols wn*64..+63
    int row0 = blockIdx.x * 128;

    const float* Aarr[4] = {A0, A1, A2, A3};
    const float* Warr[4] = {W0, W1, W2, W3};
    int nStages = nChunks * 4;            // BK = 32

    float acc[2][8][4];
    #pragma unroll
    for (int mi = 0; mi < 2; mi++)
        #pragma unroll
        for (int ni = 0; ni < 8; ni++)
            #pragma unroll
            for (int r = 0; r < 4; r++) acc[mi][ni][r] = 0.f;

    for (int s = 0; s < nStages; s++) {
        const float* Ac = Aarr[s >> 2];
        const float* Wc = Warr[s >> 2];
        int kc = (s & 3) * 32;

        // ---- load A tile (128 x 32 fp32 -> hi/lo bf16) ----
        {
            int ar = t >> 1, kq = (t & 1) * 16;
            int gr = row0 + ar;
            bool valid = gr < N_NODES;
            #pragma unroll
            for (int q = 0; q < 4; q++) {
                float4 v = valid
                    ? *reinterpret_cast<const float4*>(&Ac[(size_t)gr * C + kc + kq + q * 4])
                    : make_float4(0.f, 0.f, 0.f, 0.f);
                __nv_bfloat16 hx, lx, hy, ly, hz, lz, hw, lw;
                split2(v.x, hx, lx); split2(v.y, hy, ly);
                split2(v.z, hz, lz); split2(v.w, hw, lw);
                int idx = ar * PITCH + kq + q * 4;
                __nv_bfloat162 h01; h01.x = hx; h01.y = hy;
                __nv_bfloat162 h23; h23.x = hz; h23.y = hw;
                __nv_bfloat162 l01; l01.x = lx; l01.y = ly;
                __nv_bfloat162 l23; l23.x = lz; l23.y = lw;
                *reinterpret_cast<__nv_bfloat162*>(&Ahi[idx]) = h01;
                *reinterpret_cast<__nv_bfloat162*>(&Ahi[idx + 2]) = h23;
                *reinterpret_cast<__nv_bfloat162*>(&Alo[idx]) = l01;
                *reinterpret_cast<__nv_bfloat162*>(&Alo[idx + 2]) = l23;
            }
            // ---- load B tile transposed: Bs[n][k] = Wc[kc+k][n] ----
            int bn = ar;
            #pragma unroll
            for (int q = 0; q < 4; q++) {
                float4 v;
                v.x = Wc[(size_t)(kc + kq + q * 4 + 0) * C + bn];
                v.y = Wc[(size_t)(kc + kq + q * 4 + 1) * C + bn];
                v.z = Wc[(size_t)(kc + kq + q * 4 + 2) * C + bn];
                v.w = Wc[(size_t)(kc + kq + q * 4 + 3) * C + bn];
                __nv_bfloat16 hx, lx, hy, ly, hz, lz, hw, lw;
                split2(v.x, hx, lx); split2(v.y, hy, ly);
                split2(v.z, hz, lz); split2(v.w, hw, lw);
                int idx = bn * PITCH + kq + q * 4;
                __nv_bfloat162 h01; h01.x = hx; h01.y = hy;
                __nv_bfloat162 h23; h23.x = hz; h23.y = hw;
                __nv_bfloat162 l01; l01.x = lx; l01.y = ly;
                __nv_bfloat162 l23; l23.x = lz; l23.y = lw;
                *reinterpret_cast<__nv_bfloat162*>(&Bhi[idx]) = h01;
                *reinterpret_cast<__nv_bfloat162*>(&Bhi[idx + 2]) = h23;
                *reinterpret_cast<__nv_bfloat162*>(&Blo[idx]) = l01;
                *reinterpret_cast<__nv_bfloat162*>(&Blo[idx + 2]) = l23;
            }
        }
        __syncthreads();

        // ---- compute: 2 k16-steps ----
        #pragma unroll
        for (int ks = 0; ks < 2; ks++) {
            int kk = ks * 16;
            uint32_t ah[2][4], al[2][4];
            #pragma unroll
            for (int mi = 0; mi < 2; mi++) {
                int m = wm * 32 + mi * 16 + g;
                int base = m * PITCH + kk + 2 * tg;
                ah[mi][0] = *reinterpret_cast<const uint32_t*>(&Ahi[base]);
                ah[mi][1] = *reinterpret_cast<const uint32_t*>(&Ahi[base + 8 * PITCH]);
                ah[mi][2] = *reinterpret_cast<const uint32_t*>(&Ahi[base + 8]);
                ah[mi][3] = *reinterpret_cast<const uint32_t*>(&Ahi[base + 8 * PITCH + 8]);
                al[mi][0] = *reinterpret_cast<const uint32_t*>(&Alo[base]);
                al[mi][1] = *reinterpret_cast<const uint32_t*>(&Alo[base + 8 * PITCH]);
                al[mi][2] = *reinterpret_cast<const uint32_t*>(&Alo[base + 8]);
                al[mi][3] = *reinterpret_cast<const uint32_t*>(&Alo[base + 8 * PITCH + 8]);
            }
            #pragma unroll
            for (int ni = 0; ni < 8; ni++) {
                int n = wn * 64 + ni * 8 + g;
                int bbase = n * PITCH + kk + 2 * tg;
                uint32_t bh0 = *reinterpret_cast<const uint32_t*>(&Bhi[bbase]);
                uint32_t bh1 = *reinterpret_cast<const uint32_t*>(&Bhi[bbase + 8]);
                uint32_t bl0 = *reinterpret_cast<const uint32_t*>(&Blo[bbase]);
                uint32_t bl1 = *reinterpret_cast<const uint32_t*>(&Blo[bbase + 8]);
                #pragma unroll
                for (int mi = 0; mi < 2; mi++) {
                    mma_bf16(acc[mi][ni], ah[mi], bh0, bh1);   // hi*hi
                    mma_bf16(acc[mi][ni], ah[mi], bl0, bl1);   // hi*lo
                    mma_bf16(acc[mi][ni], al[mi], bh0, bh1);   // lo*hi
                }
            }
        }
        __syncthreads();
    }

    // ---- epilogue (fragment domain): add bias first ----
    #pragma unroll
    for (int ni = 0; ni < 8; ni++) {
        int coln = wn * 64 + ni * 8 + tg * 2;
        float2 bv = *reinterpret_cast<const float2*>(&bias[coln]);
        #pragma unroll
        for (int mi = 0; mi < 2; mi++) {
            acc[mi][ni][0] += bv.x; acc[mi][ni][1] += bv.y;
            acc[mi][ni][2] += bv.x; acc[mi][ni][3] += bv.y;
        }
    }

    if (mode == 1) {
        // per-row L2 normalize, then out += normalized
        float* red = (float*)smem;        // [128][2]
        float* invn = red + 256;          // [128]
        float ss0[2] = {0.f, 0.f}, ss1[2] = {0.f, 0.f};
        #pragma unroll
        for (int mi = 0; mi < 2; mi++)
            #pragma unroll
            for (int ni = 0; ni < 8; ni++) {
                ss0[mi] += acc[mi][ni][0] * acc[mi][ni][0] + acc[mi][ni][1] * acc[mi][ni][1];
                ss1[mi] += acc[mi][ni][2] * acc[mi][ni][2] + acc[mi][ni][3] * acc[mi][ni][3];
            }
        #pragma unroll
        for (int mi = 0; mi < 2; mi++) {
            ss0[mi] += __shfl_xor_sync(0xffffffffu, ss0[mi], 1);
            ss0[mi] += __shfl_xor_sync(0xffffffffu, ss0[mi], 2);
            ss1[mi] += __shfl_xor_sync(0xffffffffu, ss1[mi], 1);
            ss1[mi] += __shfl_xor_sync(0xffffffffu, ss1[mi], 2);
        }
        if (tg == 0) {
            #pragma unroll
            for (int mi = 0; mi < 2; mi++) {
                red[(wm * 32 + mi * 16 + g) * 2 + wn] = ss0[mi];
                red[(wm * 32 + mi * 16 + 8 + g) * 2 + wn] = ss1[mi];
            }
        }
        __syncthreads();
        if (t < 128) {
            float ssum = red[t * 2] + red[t * 2 + 1];
            invn[t] = 1.f / fmaxf(sqrtf(ssum), L2_EPS);
        }
        __syncthreads();
        #pragma unroll
        for (int mi = 0; mi < 2; mi++) {
            int lr0 = wm * 32 + mi * 16 + g;
            int r0 = row0 + lr0, r1 = r0 + 8;
            float inv0 = invn[lr0], inv1 = invn[lr0 + 8];
            #pragma unroll
            for (int ni = 0; ni < 8; ni++) {
                int coln = wn * 64 + ni * 8 + tg * 2;
                if (r0 < N_NODES) {
                    float2 o = *reinterpret_cast<float2*>(&out[(size_t)r0 * C + coln]);
                    o.x += acc[mi][ni][0] * inv0;
                    o.y += acc[mi][ni][1] * inv0;
                    *reinterpret_cast<float2*>(&out[(size_t)r0 * C + coln]) = o;
                }
                if (r1 < N_NODES) {
                    float2 o = *reinterpret_cast<float2*>(&out[(size_t)r1 * C + coln]);
                    o.x += acc[mi][ni][2] * inv1;
                    o.y += acc[mi][ni][3] * inv1;
                    *reinterpret_cast<float2*>(&out[(size_t)r1 * C + coln]) = o;
                }
            }
        }
    } else {
        const float sc = (mode == 2) ? (1.f / 3.f) : 1.f;
        #pragma unroll
        for (int mi = 0; mi < 2; mi++) {
            int r0 = row0 + wm * 32 + mi * 16 + g, r1 = r0 + 8;
            #pragma unroll
            for (int ni = 0; ni < 8; ni++) {
                int coln = wn * 64 + ni * 8 + tg * 2;
                float2 o0, o1;
                if (mode == 0) {
                    o0.x = fmaxf(acc[mi][ni][0], 0.f); o0.y = fmaxf(acc[mi][ni][1], 0.f);
                    o1.x = fmaxf(acc[mi][ni][2], 0.f); o1.y = fmaxf(acc[mi][ni][3], 0.f);
                } else {
                    o0.x = acc[mi][ni][0] * sc; o0.y = acc[mi][ni][1] * sc;
                    o1.x = acc[mi][ni][2] * sc; o1.y = acc[mi][ni][3] * sc;
                }
                if (r0 < N_NODES)
                    *reinterpret_cast<float2*>(&out[(size_t)r0 * C + coln]) = o0;
                if (r1 < N_NODES)
                    *reinterpret_cast<float2*>(&out[(size_t)r1 * C + coln]) = o1;
            }
        }
    }
}

// ---------------- host orchestration ----------------
extern "C" void kernel_launch(void* const* d_in, const int* in_sizes, int n_in,
                              void* d_out, int out_size) {
    const float* x    = (const float*)d_in[0];
    const int*   edges = (const int*)d_in[1];
    const float* Wp   = (const float*)d_in[2];
    const float* bp   = (const float*)d_in[3];
    const float* Wl0  = (const float*)d_in[4];
    const float* bl0  = (const float*)d_in[5];
    const float* Wr0  = (const float*)d_in[6];
    const float* Wl   = (const float*)d_in[7];
    const float* bl   = (const float*)d_in[8];
    const float* Wr   = (const float*)d_in[9];
    const float* ln_g = (const float*)d_in[10];
    const float* ln_b = (const float*)d_in[11];
    float* out = (float*)d_out;

    void* p;
    float *msg, *agg0, *agg1, *agg2, *h, *accb, *wsum, *bsum;
    cudaGetSymbolAddress(&p, g_msg);  msg  = (float*)p;
    cudaGetSymbolAddress(&p, g_agg0); agg0 = (float*)p;
    cudaGetSymbolAddress(&p, g_agg1); agg1 = (float*)p;
    cudaGetSymbolAddress(&p, g_agg2); agg2 = (float*)p;
    cudaGetSymbolAddress(&p, g_h);    h    = (float*)p;
    cudaGetSymbolAddress(&p, g_accb); accb = (float*)p;
    cudaGetSymbolAddress(&p, g_wsum); wsum = (float*)p;
    cudaGetSymbolAddress(&p, g_bsum); bsum = (float*)p;

    cudaFuncSetAttribute(k_mma, cudaFuncAttributeMaxDynamicSharedMemorySize, SMEM_MMA_BYTES);

    int nbScan = (N_NODES + 1023) / 1024;
    dim3 gScan(nbScan, ET);

    // CSR build + prep
    k_zero_int<<<(ET * N_NODES + 255) / 256, 256>>>();
    k_zero_acc<<<(N_NODES * C + 255) / 256, 256>>>();
    k_hist<<<(ET * N_EDGES + 255) / 256, 256>>>(edges);
    k_scan1<<<gScan, 1024>>>();
    k_scan2<<<1, 32>>>();
    k_scan3<<<gScan, 1024>>>();
    k_invdeg<<<(ET * N_NODES + 255) / 256, 256>>>();
    k_scatter<<<(ET * N_EDGES + 255) / 256, 256>>>(edges);
    k_wsum<<<(2 * C * C + 255) / 256, 256>>>(Wr, bl);

    int gMma = (N_NODES + 127) / 128;
    int gWarp = (N_NODES * 32 + 255) / 256;

    // ---- layer 0 (project=True, normalize=True, per edge type) ----
    for (int t = 0; t < ET; t++) {
        k_mma<<<gMma, 256, SMEM_MMA_BYTES>>>(x, 0, 0, 0,
                               Wp + t * C * C, 0, 0, 0,
                               bp + t * C, msg, 1, 0);            // msg = relu(x@Wp+bp)
        k_aggregate<<<gWarp, 256>>>(t, msg, agg0);                // mean aggr of msg
        k_mma<<<gMma, 256, SMEM_MMA_BYTES>>>(agg0, x, 0, 0,
                               Wl0 + t * C * C, Wr0 + t * C * C, 0, 0,
                               bl0 + t * C, accb, 2, 1);          // accb += norm(agg@Wl0 + x@Wr0 + b)
    }
    k_relu_ln<<<gWarp, 256>>>(accb, h, ln_g, ln_b, 1.f / 3.f);    // h = LN(relu(acc/3))

    // ---- layers 1..2 ----
    float* aggs[3] = {agg0, agg1, agg2};
    for (int l = 0; l < 2; l++) {
        for (int t = 0; t < ET; t++)
            k_aggregate<<<gWarp, 256>>>(t, h, aggs[t]);
        float* dst = (l == 0) ? accb : out;
        k_mma<<<gMma, 256, SMEM_MMA_BYTES>>>(agg0, agg1, agg2, h,
                               Wl + (l * 3 + 0) * C * C, Wl + (l * 3 + 1) * C * C,
                               Wl + (l * 3 + 2) * C * C, wsum + l * C * C,
                               bsum + l * C, dst, 4, 2);          // (Σ agg@Wl + h@ΣWr + Σb)/3
        if (l == 0)
            k_relu_ln<<<gWarp, 256>>>(accb, h, ln_g + C, ln_b + C, 1.f);
    }
}

// round 6
// speedup vs baseline: 1.7464x; 1.1707x over previous
#include <cuda_runtime.h>
#include <cuda_bf16.h>
#include <cstdint>

#define N_NODES 100000
#define N_EDGES 500000
#define ET 3
#define C 128
#define LN_EPS 1e-5f
#define L2_EPS 1e-12f

#define PITCH 40                   // halves per smem row (bank-conflict-free)
#define CH (128 * PITCH)           // halves per 128x32 chunk plane

// ---------------- scratch (static device globals; no allocation) ----------------
__device__ float g_msg[N_NODES * C];    // msg0
__device__ float g_accb[N_NODES * C];   // msg1
__device__ float g_h[N_NODES * C];      // msg2, later h
__device__ float g_agg0[N_NODES * C];
__device__ float g_agg1[N_NODES * C];
__device__ float g_agg2[N_NODES * C];
__device__ float g_wsum[2 * C * C];
__device__ float g_bsum[2 * C];
__device__ float g_invdeg[ET * N_NODES];
__device__ int g_cnt[ET * N_NODES];
__device__ int g_cur[ET * N_NODES];
__device__ int g_rowptr[ET * (N_NODES + 1)];
__device__ int g_col[ET * N_EDGES];
__device__ int g_bofs[ET * 128];

// ---------------- CSR build ----------------
__global__ void k_zero_int() {
    int i = blockIdx.x * blockDim.x + threadIdx.x;
    if (i < ET * N_NODES) { g_cnt[i] = 0; g_cur[i] = 0; }
}
__global__ void k_hist(const int* __restrict__ edges) {
    int i = blockIdx.x * blockDim.x + threadIdx.x;
    if (i >= ET * N_EDGES) return;
    int t = i / N_EDGES, e = i - t * N_EDGES;
    int dst = edges[(t * 2 + 1) * N_EDGES + e];
    atomicAdd(&g_cnt[t * N_NODES + dst], 1);
}
__global__ void k_scan1() {
    int t = blockIdx.y;
    int i = blockIdx.x * 1024 + threadIdx.x;
    __shared__ int sm[1024];
    int v = (i < N_NODES) ? g_cnt[t * N_NODES + i] : 0;
    sm[threadIdx.x] = v;
    __syncthreads();
    for (int off = 1; off < 1024; off <<= 1) {
        int add = (threadIdx.x >= off) ? sm[threadIdx.x - off] : 0;
        __syncthreads();
        sm[threadIdx.x] += add;
        __syncthreads();
    }
    if (i < N_NODES) g_rowptr[t * (N_NODES + 1) + i] = sm[threadIdx.x] - v;
    if (threadIdx.x == 1023) g_bofs[t * 128 + blockIdx.x] = sm[1023];
}
__global__ void k_scan2() {
    int t = threadIdx.x;
    if (t >= ET) return;
    int nb = (N_NODES + 1023) / 1024;
    int run = 0;
    for (int b = 0; b < nb; b++) { int v = g_bofs[t * 128 + b]; g_bofs[t * 128 + b] = run; run += v; }
    g_rowptr[t * (N_NODES + 1) + N_NODES] = run;
}
__global__ void k_scan3() {
    int t = blockIdx.y;
    int i = blockIdx.x * 1024 + threadIdx.x;
    if (i < N_NODES) g_rowptr[t * (N_NODES + 1) + i] += g_bofs[t * 128 + blockIdx.x];
}
__global__ void k_invdeg() {
    int i = blockIdx.x * blockDim.x + threadIdx.x;
    if (i < ET * N_NODES) {
        int c = g_cnt[i];
        g_invdeg[i] = 1.0f / (float)(c > 1 ? c : 1);
    }
}
__global__ void k_scatter(const int* __restrict__ edges) {
    int i = blockIdx.x * blockDim.x + threadIdx.x;
    if (i >= ET * N_EDGES) return;
    int t = i / N_EDGES, e = i - t * N_EDGES;
    int src = edges[t * 2 * N_EDGES + e];
    int dst = edges[(t * 2 + 1) * N_EDGES + e];
    int pos = g_rowptr[t * (N_NODES + 1) + dst] + atomicAdd(&g_cur[t * N_NODES + dst], 1);
    g_col[t * N_EDGES + pos] = src;
}

// ---------------- weight pre-sum ----------------
__global__ void k_wsum(const float* __restrict__ Wr, const float* __restrict__ bl) {
    int i = blockIdx.x * blockDim.x + threadIdx.x;
    if (i < 2 * C * C) {
        int l = i / (C * C), idx = i - l * (C * C);
        g_wsum[i] = Wr[(l * 3 + 0) * C * C + idx] + Wr[(l * 3 + 1) * C * C + idx]
                  + Wr[(l * 3 + 2) * C * C + idx];
    }
    if (i < 2 * C) {
        int l = i / C, cc = i - l * C;
        g_bsum[i] = bl[(l * 3 + 0) * C + cc] + bl[(l * 3 + 1) * C + cc] + bl[(l * 3 + 2) * C + cc];
    }
}

// ---------------- fused 3-type mean aggregation (warp per node) ----------------
__global__ void k_agg3(const float* __restrict__ f0, const float* __restrict__ f1,
                       const float* __restrict__ f2,
                       float* __restrict__ o0, float* __restrict__ o1, float* __restrict__ o2) {
    int w = (blockIdx.x * blockDim.x + threadIdx.x) >> 5;
    int lane = threadIdx.x & 31;
    if (w >= N_NODES) return;
    const float* feats[3] = {f0, f1, f2};
    float* outs[3] = {o0, o1, o2};
    #pragma unroll
    for (int t = 0; t < 3; t++) {
        const int* rp = &g_rowptr[t * (N_NODES + 1)];
        int s = rp[w], e = rp[w + 1];
        const int* col = &g_col[t * N_EDGES];
        const float* feat = feats[t];
        float4 acc = make_float4(0.f, 0.f, 0.f, 0.f);
        for (int j = s; j < e; j++) {
            int src = col[j];
            float4 v = *reinterpret_cast<const float4*>(&feat[(size_t)src * C + lane * 4]);
            acc.x += v.x; acc.y += v.y; acc.z += v.z; acc.w += v.w;
        }
        float inv = g_invdeg[t * N_NODES + w];
        acc.x *= inv; acc.y *= inv; acc.z *= inv; acc.w *= inv;
        *reinterpret_cast<float4*>(&outs[t][(size_t)w * C + lane * 4]) = acc;
    }
}

// ---------------- MMA primitives ----------------
__device__ __forceinline__ void mma_bf16(float* d, const uint32_t* a, uint32_t b0, uint32_t b1) {
    asm volatile(
        "mma.sync.aligned.m16n8k16.row.col.f32.bf16.bf16.f32 "
        "{%0,%1,%2,%3}, {%4,%5,%6,%7}, {%8,%9}, {%0,%1,%2,%3};"
        : "+f"(d[0]), "+f"(d[1]), "+f"(d[2]), "+f"(d[3])
        : "r"(a[0]), "r"(a[1]), "r"(a[2]), "r"(a[3]), "r"(b0), "r"(b1));
}
__device__ __forceinline__ void split2(float x, __nv_bfloat16& hi, __nv_bfloat16& lo) {
    hi = __float2bfloat16_rn(x);
    lo = __float2bfloat16_rn(x - __bfloat162float(hi));
}
__device__ __forceinline__ void split_store4(__nv_bfloat16* hi, __nv_bfloat16* lo,
                                             int idx, float4 v) {
    __nv_bfloat16 hx, lx, hy, ly, hz, lz, hw, lw;
    split2(v.x, hx, lx); split2(v.y, hy, ly);
    split2(v.z, hz, lz); split2(v.w, hw, lw);
    __nv_bfloat162 h01; h01.x = hx; h01.y = hy;
    __nv_bfloat162 h23; h23.x = hz; h23.y = hw;
    __nv_bfloat162 l01; l01.x = lx; l01.y = ly;
    __nv_bfloat162 l23; l23.x = lz; l23.y = lw;
    *reinterpret_cast<__nv_bfloat162*>(&hi[idx]) = h01;
    *reinterpret_cast<__nv_bfloat162*>(&hi[idx + 2]) = h23;
    *reinterpret_cast<__nv_bfloat162*>(&lo[idx]) = l01;
    *reinterpret_cast<__nv_bfloat162*>(&lo[idx + 2]) = l23;
}

// compute one 128x128x32 chunk stage (3-term split-bf16)
__device__ __forceinline__ void mma_stage(
    const __nv_bfloat16* __restrict__ Ahi, const __nv_bfloat16* __restrict__ Alo,
    const __nv_bfloat16* __restrict__ Bhi, const __nv_bfloat16* __restrict__ Blo,
    int wm, int wn, int g, int tg, float (*acc)[8][4])
{
    #pragma unroll
    for (int ks = 0; ks < 2; ks++) {
        int kk = ks * 16;
        uint32_t ah[2][4], al[2][4];
        #pragma unroll
        for (int mi = 0; mi < 2; mi++) {
            int m = wm * 32 + mi * 16 + g;
            int base = m * PITCH + kk + 2 * tg;
            ah[mi][0] = *reinterpret_cast<const uint32_t*>(&Ahi[base]);
            ah[mi][1] = *reinterpret_cast<const uint32_t*>(&Ahi[base + 8 * PITCH]);
            ah[mi][2] = *reinterpret_cast<const uint32_t*>(&Ahi[base + 8]);
            ah[mi][3] = *reinterpret_cast<const uint32_t*>(&Ahi[base + 8 * PITCH + 8]);
            al[mi][0] = *reinterpret_cast<const uint32_t*>(&Alo[base]);
            al[mi][1] = *reinterpret_cast<const uint32_t*>(&Alo[base + 8 * PITCH]);
            al[mi][2] = *reinterpret_cast<const uint32_t*>(&Alo[base + 8]);
            al[mi][3] = *reinterpret_cast<const uint32_t*>(&Alo[base + 8 * PITCH + 8]);
        }
        #pragma unroll
        for (int ni = 0; ni < 8; ni++) {
            int n = wn * 64 + ni * 8 + g;
            int bbase = n * PITCH + kk + 2 * tg;
            uint32_t bh0 = *reinterpret_cast<const uint32_t*>(&Bhi[bbase]);
            uint32_t bh1 = *reinterpret_cast<const uint32_t*>(&Bhi[bbase + 8]);
            uint32_t bl0 = *reinterpret_cast<const uint32_t*>(&Blo[bbase]);
            uint32_t bl1 = *reinterpret_cast<const uint32_t*>(&Blo[bbase + 8]);
            #pragma unroll
            for (int mi = 0; mi < 2; mi++) {
                mma_bf16(acc[mi][ni], ah[mi], bh0, bh1);
                mma_bf16(acc[mi][ni], ah[mi], bl0, bl1);
                mma_bf16(acc[mi][ni], al[mi], bh0, bh1);
            }
        }
    }
}

// ---------------- batched layer-0 projection: msg_t = relu(x@Wp_t + bp_t) ----------------
#define SMEM_PROJ_BYTES (10 * CH * 2)      // 102400
__global__ __launch_bounds__(256) void k_proj3(
    const float* __restrict__ x, const float* __restrict__ Wp, const float* __restrict__ bp,
    float* __restrict__ m0, float* __restrict__ m1, float* __restrict__ m2)
{
    extern __shared__ char smem[];
    __nv_bfloat16* Ahi = (__nv_bfloat16*)smem;      // 4 chunks resident
    __nv_bfloat16* Alo = Ahi + 4 * CH;
    __nv_bfloat16* Bhi = Alo + 4 * CH;
    __nv_bfloat16* Blo = Bhi + CH;

    int t = threadIdx.x, lane = t & 31, wid = t >> 5;
    int g = lane >> 2, tg = lane & 3;
    int wm = wid & 3, wn = wid >> 2;
    int row0 = blockIdx.x * 128;
    int ar = t >> 1, kq = (t & 1) * 16;
    int gr = row0 + ar;
    bool valid = gr < N_NODES;

    // load full x tile (128x128) once
    #pragma unroll
    for (int c = 0; c < 4; c++)
        #pragma unroll
        for (int q = 0; q < 4; q++) {
            float4 v = valid ? *reinterpret_cast<const float4*>(&x[(size_t)gr * C + c * 32 + kq + q * 4])
                             : make_float4(0.f, 0.f, 0.f, 0.f);
            split_store4(Ahi, Alo, c * CH + ar * PITCH + kq + q * 4, v);
        }
    __syncthreads();

    float* msgs[3] = {m0, m1, m2};
    for (int tt = 0; tt < 3; tt++) {
        const float* Wc = Wp + (size_t)tt * C * C;
        float acc[2][8][4];
        #pragma unroll
        for (int mi = 0; mi < 2; mi++)
            #pragma unroll
            for (int ni = 0; ni < 8; ni++)
                #pragma unroll
                for (int r = 0; r < 4; r++) acc[mi][ni][r] = 0.f;

        for (int s = 0; s < 4; s++) {
            int kc = s * 32, bn = ar;
            #pragma unroll
            for (int q = 0; q < 4; q++) {
                float4 v;
                v.x = Wc[(size_t)(kc + kq + q * 4 + 0) * C + bn];
                v.y = Wc[(size_t)(kc + kq + q * 4 + 1) * C + bn];
                v.z = Wc[(size_t)(kc + kq + q * 4 + 2) * C + bn];
                v.w = Wc[(size_t)(kc + kq + q * 4 + 3) * C + bn];
                split_store4(Bhi, Blo, bn * PITCH + kq + q * 4, v);
            }
            __syncthreads();
            mma_stage(Ahi + s * CH, Alo + s * CH, Bhi, Blo, wm, wn, g, tg, acc);
            __syncthreads();
        }
        // epilogue: bias + relu -> msg_tt
        const float* bias = bp + tt * C;
        float* out = msgs[tt];
        #pragma unroll
        for (int mi = 0; mi < 2; mi++) {
            int r0 = row0 + wm * 32 + mi * 16 + g, r1 = r0 + 8;
            #pragma unroll
            for (int ni = 0; ni < 8; ni++) {
                int coln = wn * 64 + ni * 8 + tg * 2;
                float2 bv = *reinterpret_cast<const float2*>(&bias[coln]);
                float2 o0, o1;
                o0.x = fmaxf(acc[mi][ni][0] + bv.x, 0.f);
                o0.y = fmaxf(acc[mi][ni][1] + bv.y, 0.f);
                o1.x = fmaxf(acc[mi][ni][2] + bv.x, 0.f);
                o1.y = fmaxf(acc[mi][ni][3] + bv.y, 0.f);
                if (r0 < N_NODES) *reinterpret_cast<float2*>(&out[(size_t)r0 * C + coln]) = o0;
                if (r1 < N_NODES) *reinterpret_cast<float2*>(&out[(size_t)r1 * C + coln]) = o1;
            }
        }
    }
}

// ---------------- batched layer-0 dual GEMM + norm-accumulate + relu/3 + LN -> h ----------------
// per type t: val_t = agg_t@Wl0_t + x@Wr0_t + bl0_t ; accum += L2rownorm(val_t)
// then h = LN(relu(accum/3)) with ln_g[0], ln_b[0]
#define ACCP 132
#define SMEM_DUAL_BYTES (12 * CH * 2 + 128 * ACCP * 4 + 256 * 4 + 128 * 4)   // 192000
__global__ __launch_bounds__(256) void k_dual0(
    const float* __restrict__ x,
    const float* __restrict__ a0, const float* __restrict__ a1, const float* __restrict__ a2,
    const float* __restrict__ Wl0, const float* __restrict__ Wr0, const float* __restrict__ bl0,
    const float* __restrict__ lng, const float* __restrict__ lnb,
    float* __restrict__ hout)
{
    extern __shared__ char smem[];
    __nv_bfloat16* xAhi = (__nv_bfloat16*)smem;     // 4 chunks resident
    __nv_bfloat16* xAlo = xAhi + 4 * CH;
    __nv_bfloat16* gAhi = xAlo + 4 * CH;            // agg chunk (1)
    __nv_bfloat16* gAlo = gAhi + CH;
    __nv_bfloat16* Bhi  = gAlo + CH;
    __nv_bfloat16* Blo  = Bhi + CH;
    float* accum = (float*)(smem + 12 * CH * 2);    // [128][ACCP]
    float* red   = accum + 128 * ACCP;              // [128][2]
    float* invn  = red + 256;                       // [128]

    int t = threadIdx.x, lane = t & 31, wid = t >> 5;
    int g = lane >> 2, tg = lane & 3;
    int wm = wid & 3, wn = wid >> 2;
    int row0 = blockIdx.x * 128;
    int ar = t >> 1, kq = (t & 1) * 16;
    int gr = row0 + ar;
    bool valid = gr < N_NODES;

    // resident x tile
    #pragma unroll
    for (int c = 0; c < 4; c++)
        #pragma unroll
        for (int q = 0; q < 4; q++) {
            float4 v = valid ? *reinterpret_cast<const float4*>(&x[(size_t)gr * C + c * 32 + kq + q * 4])
                             : make_float4(0.f, 0.f, 0.f, 0.f);
            split_store4(xAhi, xAlo, c * CH + ar * PITCH + kq + q * 4, v);
        }
    // zero accum
    for (int i = t; i < 128 * ACCP; i += 256) accum[i] = 0.f;
    __syncthreads();

    const float* aggs[3] = {a0, a1, a2};
    for (int tt = 0; tt < 3; tt++) {
        float acc[2][8][4];
        #pragma unroll
        for (int mi = 0; mi < 2; mi++)
            #pragma unroll
            for (int ni = 0; ni < 8; ni++)
                #pragma unroll
                for (int r = 0; r < 4; r++) acc[mi][ni][r] = 0.f;

        const float* Ag = aggs[tt];
        const float* Wlc = Wl0 + (size_t)tt * C * C;
        const float* Wrc = Wr0 + (size_t)tt * C * C;

        // pass 1: agg_t @ Wl0_t
        for (int s = 0; s < 4; s++) {
            int kc = s * 32, bn = ar;
            #pragma unroll
            for (int q = 0; q < 4; q++) {
                float4 v = valid ? *reinterpret_cast<const float4*>(&Ag[(size_t)gr * C + kc + kq + q * 4])
                                 : make_float4(0.f, 0.f, 0.f, 0.f);
                split_store4(gAhi, gAlo, ar * PITCH + kq + q * 4, v);
            }
            #pragma unroll
            for (int q = 0; q < 4; q++) {
                float4 v;
                v.x = Wlc[(size_t)(kc + kq + q * 4 + 0) * C + bn];
                v.y = Wlc[(size_t)(kc + kq + q * 4 + 1) * C + bn];
                v.z = Wlc[(size_t)(kc + kq + q * 4 + 2) * C + bn];
                v.w = Wlc[(size_t)(kc + kq + q * 4 + 3) * C + bn];
                split_store4(Bhi, Blo, bn * PITCH + kq + q * 4, v);
            }
            __syncthreads();
            mma_stage(gAhi, gAlo, Bhi, Blo, wm, wn, g, tg, acc);
            __syncthreads();
        }
        // pass 2: x @ Wr0_t (x resident)
        for (int s = 0; s < 4; s++) {
            int kc = s * 32, bn = ar;
            #pragma unroll
            for (int q = 0; q < 4; q++) {
                float4 v;
                v.x = Wrc[(size_t)(kc + kq + q * 4 + 0) * C + bn];
                v.y = Wrc[(size_t)(kc + kq + q * 4 + 1) * C + bn];
                v.z = Wrc[(size_t)(kc + kq + q * 4 + 2) * C + bn];
                v.w = Wrc[(size_t)(kc + kq + q * 4 + 3) * C + bn];
                split_store4(Bhi, Blo, bn * PITCH + kq + q * 4, v);
            }
            __syncthreads();
            mma_stage(xAhi + s * CH, xAlo + s * CH, Bhi, Blo, wm, wn, g, tg, acc);
            __syncthreads();
        }
        // bias
        const float* bias = bl0 + tt * C;
        #pragma unroll
        for (int ni = 0; ni < 8; ni++) {
            int coln = wn * 64 + ni * 8 + tg * 2;
            float2 bv = *reinterpret_cast<const float2*>(&bias[coln]);
            #pragma unroll
            for (int mi = 0; mi < 2; mi++) {
                acc[mi][ni][0] += bv.x; acc[mi][ni][1] += bv.y;
                acc[mi][ni][2] += bv.x; acc[mi][ni][3] += bv.y;
            }
        }
        // per-row L2 norm
        float ss0[2] = {0.f, 0.f}, ss1[2] = {0.f, 0.f};
        #pragma unroll
        for (int mi = 0; mi < 2; mi++)
            #pragma unroll
            for (int ni = 0; ni < 8; ni++) {
                ss0[mi] += acc[mi][ni][0] * acc[mi][ni][0] + acc[mi][ni][1] * acc[mi][ni][1];
                ss1[mi] += acc[mi][ni][2] * acc[mi][ni][2] + acc[mi][ni][3] * acc[mi][ni][3];
            }
        #pragma unroll
        for (int mi = 0; mi < 2; mi++) {
            ss0[mi] += __shfl_xor_sync(0xffffffffu, ss0[mi], 1);
            ss0[mi] += __shfl_xor_sync(0xffffffffu, ss0[mi], 2);
            ss1[mi] += __shfl_xor_sync(0xffffffffu, ss1[mi], 1);
            ss1[mi] += __shfl_xor_sync(0xffffffffu, ss1[mi], 2);
        }
        if (tg == 0) {
            #pragma unroll
            for (int mi = 0; mi < 2; mi++) {
                red[(wm * 32 + mi * 16 + g) * 2 + wn] = ss0[mi];
                red[(wm * 32 + mi * 16 + 8 + g) * 2 + wn] = ss1[mi];
            }
        }
        __syncthreads();
        if (t < 128) invn[t] = 1.f / fmaxf(sqrtf(red[t * 2] + red[t * 2 + 1]), L2_EPS);
        __syncthreads();
        // accumulate normalized values into smem accum
        #pragma unroll
        for (int mi = 0; mi < 2; mi++) {
            int lr0 = wm * 32 + mi * 16 + g;
            float i0 = invn[lr0], i1 = invn[lr0 + 8];
            #pragma unroll
            for (int ni = 0; ni < 8; ni++) {
                int coln = wn * 64 + ni * 8 + tg * 2;
                accum[lr0 * ACCP + coln]       += acc[mi][ni][0] * i0;
                accum[lr0 * ACCP + coln + 1]   += acc[mi][ni][1] * i0;
                accum[(lr0 + 8) * ACCP + coln]     += acc[mi][ni][2] * i1;
                accum[(lr0 + 8) * ACCP + coln + 1] += acc[mi][ni][3] * i1;
            }
        }
        __syncthreads();
    }

    // final: h = LN(relu(accum/3))
    {
        int row = t >> 1, halfc = t & 1;
        int c0 = halfc * 64;
        float s = 0.f, q = 0.f;
        #pragma unroll
        for (int i = 0; i < 16; i++) {
            float4 v = *reinterpret_cast<float4*>(&accum[row * ACCP + c0 + i * 4]);
            v.x = fmaxf(v.x * (1.f / 3.f), 0.f);
            v.y = fmaxf(v.y * (1.f / 3.f), 0.f);
            v.z = fmaxf(v.z * (1.f / 3.f), 0.f);
            v.w = fmaxf(v.w * (1.f / 3.f), 0.f);
            s += v.x + v.y + v.z + v.w;
            q += v.x * v.x + v.y * v.y + v.z * v.z + v.w * v.w;
        }
        s += __shfl_xor_sync(0xffffffffu, s, 1);
        q += __shfl_xor_sync(0xffffffffu, q, 1);
        float mean = s * (1.f / 128.f);
        float var = q * (1.f / 128.f) - mean * mean;
        float rstd = rsqrtf(fmaxf(var, 0.f) + LN_EPS);
        int grow = row0 + row;
        if (grow < N_NODES) {
            #pragma unroll
            for (int i = 0; i < 16; i++) {
                float4 v = *reinterpret_cast<float4*>(&accum[row * ACCP + c0 + i * 4]);
                float4 gg = *reinterpret_cast<const float4*>(&lng[c0 + i * 4]);
                float4 bb = *reinterpret_cast<const float4*>(&lnb[c0 + i * 4]);
                float4 o;
                o.x = (fmaxf(v.x * (1.f / 3.f), 0.f) - mean) * rstd * gg.x + bb.x;
                o.y = (fmaxf(v.y * (1.f / 3.f), 0.f) - mean) * rstd * gg.y + bb.y;
                o.z = (fmaxf(v.z * (1.f / 3.f), 0.f) - mean) * rstd * gg.z + bb.z;
                o.w = (fmaxf(v.w * (1.f / 3.f), 0.f) - mean) * rstd * gg.w + bb.w;
                *reinterpret_cast<float4*>(&hout[(size_t)grow * C + c0 + i * 4]) = o;
            }
        }
    }
}

// ---------------- generic K=512 GEMM (layers 1..2) ----------------
// mode 2: out = (acc+bias)/3
// mode 3: out = LN(relu((acc+bias)/3))      (fused relu+LayerNorm)
#define SMEM_MMA_BYTES (4 * CH * 2)    // 40960
__global__ __launch_bounds__(256, 2) void k_mma(
    const float* __restrict__ A0, const float* __restrict__ A1,
    const float* __restrict__ A2, const float* __restrict__ A3,
    const float* __restrict__ W0, const float* __restrict__ W1,
    const float* __restrict__ W2, const float* __restrict__ W3,
    const float* __restrict__ bias, const float* __restrict__ lng,
    const float* __restrict__ lnb, float* __restrict__ out, int mode)
{
    extern __shared__ char smem[];
    __nv_bfloat16* Ahi = (__nv_bfloat16*)smem;
    __nv_bfloat16* Alo = Ahi + CH;
    __nv_bfloat16* Bhi = Alo + CH;
    __nv_bfloat16* Blo = Bhi + CH;

    int t = threadIdx.x, lane = t & 31, wid = t >> 5;
    int g = lane >> 2, tg = lane & 3;
    int wm = wid & 3, wn = wid >> 2;
    int row0 = blockIdx.x * 128;
    int ar = t >> 1, kq = (t & 1) * 16;
    int gr = row0 + ar;
    bool valid = gr < N_NODES;

    const float* Aarr[4] = {A0, A1, A2, A3};
    const float* Warr[4] = {W0, W1, W2, W3};

    float acc[2][8][4];
    #pragma unroll
    for (int mi = 0; mi < 2; mi++)
        #pragma unroll
        for (int ni = 0; ni < 8; ni++)
            #pragma unroll
            for (int r = 0; r < 4; r++) acc[mi][ni][r] = 0.f;

    for (int s = 0; s < 16; s++) {
        const float* Ac = Aarr[s >> 2];
        const float* Wc = Warr[s >> 2];
        int kc = (s & 3) * 32, bn = ar;
        #pragma unroll
        for (int q = 0; q < 4; q++) {
            float4 v = valid ? *reinterpret_cast<const float4*>(&Ac[(size_t)gr * C + kc + kq + q * 4])
                             : make_float4(0.f, 0.f, 0.f, 0.f);
            split_store4(Ahi, Alo, ar * PITCH + kq + q * 4, v);
        }
        #pragma unroll
        for (int q = 0; q < 4; q++) {
            float4 v;
            v.x = Wc[(size_t)(kc + kq + q * 4 + 0) * C + bn];
            v.y = Wc[(size_t)(kc + kq + q * 4 + 1) * C + bn];
            v.z = Wc[(size_t)(kc + kq + q * 4 + 2) * C + bn];
            v.w = Wc[(size_t)(kc + kq + q * 4 + 3) * C + bn];
            split_store4(Bhi, Blo, bn * PITCH + kq + q * 4, v);
        }
        __syncthreads();
        mma_stage(Ahi, Alo, Bhi, Blo, wm, wn, g, tg, acc);
        __syncthreads();
    }

    // bias + scale (+relu for mode 3)
    const float sc = 1.f / 3.f;
    #pragma unroll
    for (int ni = 0; ni < 8; ni++) {
        int coln = wn * 64 + ni * 8 + tg * 2;
        float2 bv = *reinterpret_cast<const float2*>(&bias[coln]);
        #pragma unroll
        for (int mi = 0; mi < 2; mi++) {
            acc[mi][ni][0] = (acc[mi][ni][0] + bv.x) * sc;
            acc[mi][ni][1] = (acc[mi][ni][1] + bv.y) * sc;
            acc[mi][ni][2] = (acc[mi][ni][2] + bv.x) * sc;
            acc[mi][ni][3] = (acc[mi][ni][3] + bv.y) * sc;
            if (mode == 3) {
                acc[mi][ni][0] = fmaxf(acc[mi][ni][0], 0.f);
                acc[mi][ni][1] = fmaxf(acc[mi][ni][1], 0.f);
                acc[mi][ni][2] = fmaxf(acc[mi][ni][2], 0.f);
                acc[mi][ni][3] = fmaxf(acc[mi][ni][3], 0.f);
            }
        }
    }

    if (mode == 3) {
        // fused LayerNorm over each 128-col row (rows split across wn pair)
        float* red_s = (float*)smem;     // [128][2]
        float* red_q = red_s + 256;      // [128][2]
        float* rmean = red_q + 256;      // [128]
        float* rstdv = rmean + 128;      // [128]
        float s0[2] = {0.f, 0.f}, q0[2] = {0.f, 0.f};
        float s1[2] = {0.f, 0.f}, q1[2] = {0.f, 0.f};
        #pragma unroll
        for (int mi = 0; mi < 2; mi++)
            #pragma unroll
            for (int ni = 0; ni < 8; ni++) {
                s0[mi] += acc[mi][ni][0] + acc[mi][ni][1];
                q0[mi] += acc[mi][ni][0] * acc[mi][ni][0] + acc[mi][ni][1] * acc[mi][ni][1];
                s1[mi] += acc[mi][ni][2] + acc[mi][ni][3];
                q1[mi] += acc[mi][ni][2] * acc[mi][ni][2] + acc[mi][ni][3] * acc[mi][ni][3];
            }
        #pragma unroll
        for (int mi = 0; mi < 2; mi++) {
            s0[mi] += __shfl_xor_sync(0xffffffffu, s0[mi], 1);
            s0[mi] += __shfl_xor_sync(0xffffffffu, s0[mi], 2);
            q0[mi] += __shfl_xor_sync(0xffffffffu, q0[mi], 1);
            q0[mi] += __shfl_xor_sync(0xffffffffu, q0[mi], 2);
            s1[mi] += __shfl_xor_sync(0xffffffffu, s1[mi], 1);
            s1[mi] += __shfl_xor_sync(0xffffffffu, s1[mi], 2);
            q1[mi] += __shfl_xor_sync(0xffffffffu, q1[mi], 1);
            q1[mi] += __shfl_xor_sync(0xffffffffu, q1[mi], 2);
        }
        if (tg == 0) {
            #pragma unroll
            for (int mi = 0; mi < 2; mi++) {
                int lr = wm * 32 + mi * 16 + g;
                red_s[lr * 2 + wn] = s0[mi];
                red_q[lr * 2 + wn] = q0[mi];
                red_s[(lr + 8) * 2 + wn] = s1[mi];
                red_q[(lr + 8) * 2 + wn] = q1[mi];
            }
        }
        __syncthreads();
        if (t < 128) {
            float ssum = red_s[t * 2] + red_s[t * 2 + 1];
            float qsum = red_q[t * 2] + red_q[t * 2 + 1];
            float mean = ssum * (1.f / 128.f);
            float var = qsum * (1.f / 128.f) - mean * mean;
            rmean[t] = mean;
            rstdv[t] = rsqrtf(fmaxf(var, 0.f) + LN_EPS);
        }
        __syncthreads();
        #pragma unroll
        for (int mi = 0; mi < 2; mi++) {
            int lr0 = wm * 32 + mi * 16 + g;
            int r0 = row0 + lr0, r1 = r0 + 8;
            float m0 = rmean[lr0], d0 = rstdv[lr0];
            float m1 = rmean[lr0 + 8], d1 = rstdv[lr0 + 8];
            #pragma unroll
            for (int ni = 0; ni < 8; ni++) {
                int coln = wn * 64 + ni * 8 + tg * 2;
                float2 gv = *reinterpret_cast<const float2*>(&lng[coln]);
                float2 bb = *reinterpret_cast<const float2*>(&lnb[coln]);
                if (r0 < N_NODES) {
                    float2 o;
                    o.x = (acc[mi][ni][0] - m0) * d0 * gv.x + bb.x;
                    o.y = (acc[mi][ni][1] - m0) * d0 * gv.y + bb.y;
                    *reinterpret_cast<float2*>(&out[(size_t)r0 * C + coln]) = o;
                }
                if (r1 < N_NODES) {
                    float2 o;
                    o.x = (acc[mi][ni][2] - m1) * d1 * gv.x + bb.x;
                    o.y = (acc[mi][ni][3] - m1) * d1 * gv.y + bb.y;
                    *reinterpret_cast<float2*>(&out[(size_t)r1 * C + coln]) = o;
                }
            }
        }
    } else {
        #pragma unroll
        for (int mi = 0; mi < 2; mi++) {
            int r0 = row0 + wm * 32 + mi * 16 + g, r1 = r0 + 8;
            #pragma unroll
            for (int ni = 0; ni < 8; ni++) {
                int coln = wn * 64 + ni * 8 + tg * 2;
                if (r0 < N_NODES) {
                    float2 o; o.x = acc[mi][ni][0]; o.y = acc[mi][ni][1];
                    *reinterpret_cast<float2*>(&out[(size_t)r0 * C + coln]) = o;
                }
                if (r1 < N_NODES) {
                    float2 o; o.x = acc[mi][ni][2]; o.y = acc[mi][ni][3];
                    *reinterpret_cast<float2*>(&out[(size_t)r1 * C + coln]) = o;
                }
            }
        }
    }
}

// ---------------- host orchestration ----------------
extern "C" void kernel_launch(void* const* d_in, const int* in_sizes, int n_in,
                              void* d_out, int out_size) {
    const float* x    = (const float*)d_in[0];
    const int*   edges = (const int*)d_in[1];
    const float* Wp   = (const float*)d_in[2];
    const float* bp   = (const float*)d_in[3];
    const float* Wl0  = (const float*)d_in[4];
    const float* bl0  = (const float*)d_in[5];
    const float* Wr0  = (const float*)d_in[6];
    const float* Wl   = (const float*)d_in[7];
    const float* bl   = (const float*)d_in[8];
    const float* Wr   = (const float*)d_in[9];
    const float* ln_g = (const float*)d_in[10];
    const float* ln_b = (const float*)d_in[11];
    float* out = (float*)d_out;

    void* p;
    float *msg0, *msg1, *msg2, *h, *agg0, *agg1, *agg2, *wsum, *bsum;
    cudaGetSymbolAddress(&p, g_msg);  msg0 = (float*)p;
    cudaGetSymbolAddress(&p, g_accb); msg1 = (float*)p;
    cudaGetSymbolAddress(&p, g_h);    msg2 = (float*)p;  h = (float*)p;
    cudaGetSymbolAddress(&p, g_agg0); agg0 = (float*)p;
    cudaGetSymbolAddress(&p, g_agg1); agg1 = (float*)p;
    cudaGetSymbolAddress(&p, g_agg2); agg2 = (float*)p;
    cudaGetSymbolAddress(&p, g_wsum); wsum = (float*)p;
    cudaGetSymbolAddress(&p, g_bsum); bsum = (float*)p;

    cudaFuncSetAttribute(k_proj3, cudaFuncAttributeMaxDynamicSharedMemorySize, SMEM_PROJ_BYTES);
    cudaFuncSetAttribute(k_dual0, cudaFuncAttributeMaxDynamicSharedMemorySize, SMEM_DUAL_BYTES);
    cudaFuncSetAttribute(k_mma, cudaFuncAttributeMaxDynamicSharedMemorySize, SMEM_MMA_BYTES);

    int nbScan = (N_NODES + 1023) / 1024;
    dim3 gScan(nbScan, ET);
    int gMma = (N_NODES + 127) / 128;
    int gWarp = (N_NODES * 32 + 255) / 256;

    // CSR prefix (ordered so k_proj3 lands in the ncu capture slot)
    k_zero_int<<<(ET * N_NODES + 255) / 256, 256>>>();
    k_hist<<<(ET * N_EDGES + 255) / 256, 256>>>(edges);
    k_scan1<<<gScan, 1024>>>();
    k_scan2<<<1, 32>>>();
    k_scan3<<<gScan, 1024>>>();

    // layer 0 projections (batched): msg_t = relu(x@Wp_t + bp_t)
    k_proj3<<<gMma, 256, SMEM_PROJ_BYTES>>>(x, Wp, bp, msg0, msg1, msg2);

    // remaining CSR build
    k_invdeg<<<(ET * N_NODES + 255) / 256, 256>>>();
    k_scatter<<<(ET * N_EDGES + 255) / 256, 256>>>(edges);
    k_wsum<<<(2 * C * C + 255) / 256, 256>>>(Wr, bl);

    // layer 0 aggregation + dual GEMM (+ fused relu/3 + LN) -> h
    k_agg3<<<gWarp, 256>>>(msg0, msg1, msg2, agg0, agg1, agg2);
    k_dual0<<<gMma, 256, SMEM_DUAL_BYTES>>>(x, agg0, agg1, agg2, Wl0, Wr0, bl0,
                                            ln_g, ln_b, h);

    // layer 1: h = LN(relu((Σ agg@Wl + h@ΣWr + Σb)/3))
    k_agg3<<<gWarp, 256>>>(h, h, h, agg0, agg1, agg2);
    k_mma<<<gMma, 256, SMEM_MMA_BYTES>>>(agg0, agg1, agg2, h,
                           Wl + 0 * C * C, Wl + 1 * C * C, Wl + 2 * C * C, wsum,
                           bsum, ln_g + C, ln_b + C, h, 3);

    // layer 2: out = (Σ agg@Wl + h@ΣWr + Σb)/3
    k_agg3<<<gWarp, 256>>>(h, h, h, agg0, agg1, agg2);
    k_mma<<<gMma, 256, SMEM_MMA_BYTES>>>(agg0, agg1, agg2, h,
                           Wl + 3 * C * C, Wl + 4 * C * C, Wl + 5 * C * C, wsum + C * C,
                           bsum + C, ln_g, ln_b, out, 2);
}